// round 12
// baseline (speedup 1.0000x reference)
#include <cuda_runtime.h>
#include <cstdint>

// FeedForwardNet_72335839199562 — NEAT feed-forward DAG scan, v4.
// Binder identified in R11: L1tex wavefront BW, 16x duplicated W reads
// (16 warps x same 12 W rows = 98KB L1/chunk = 768cyc vs 384 FMA budget).
// v4 halves duplication: 8 warps x 4 batch rows each (TB=32, 128 CTAs).
//   per chunk/SM: FMA 256 cyc == W-L1 256 cyc (co-balanced), LDS 128 cyc.
// Acts: evaluated cols in 192KB smem (warp-private rows, LDS.128);
//       input cols held ENTIRELY in registers (64 regs/thread, loaded once)
//       -> zero part-A act traffic. W first-touch hidden by warp-0
//       prefetch.global.L1 one chunk ahead. Packed fma.rn.f32x2 throughout.
// Per group G=8: dense chunks -> butterfly reduce -> serial triangular tail
// (redundant on all lanes; in-group 8x8 W block double-buffered in smem).

#define N_IN    512
#define N_NODES 2048
#define N_EVAL  1536
#define N_OUT   256
#define TB      32
#define G       8
#define NGROUPS (N_EVAL / G)     // 192
#define THREADS 256              // 8 warps; warp w owns rows 4w..4w+3
#define EVS     1536             // smem row stride (floats)

typedef unsigned long long ull;

__device__ __forceinline__ float sigmoid5(float z) {
    float t = fminf(fmaxf(5.0f * z, -60.0f), 60.0f);
    return 1.0f / (1.0f + __expf(-t));
}

__device__ __forceinline__ ull ffma2(ull a, ull b, ull c) {
    ull d;
    asm("fma.rn.f32x2 %0, %1, %2, %3;" : "=l"(d) : "l"(a), "l"(b), "l"(c));
    return d;
}
__device__ __forceinline__ float lo32(ull v) { return __uint_as_float((unsigned)v); }
__device__ __forceinline__ float hi32(ull v) { return __uint_as_float((unsigned)(v >> 32)); }

__device__ __forceinline__ void l1_prefetch(const float* p) {
    asm volatile("prefetch.global.L1 [%0];" :: "l"(p));
}

__global__ __launch_bounds__(THREADS, 1)
void neat_scan_kernel(const float* __restrict__ x,
                      const float* __restrict__ W,
                      const float* __restrict__ b,
                      float* __restrict__ out)
{
    extern __shared__ float sEval[];            // [TB][EVS] evaluated acts
    __shared__ float sWblk[2][G][G + 1];        // in-group W block, dbl-buf

    const int tid  = threadIdx.x;
    const int warp = tid >> 5;
    const int lane = tid & 31;
    const int rowBase = blockIdx.x * TB;

    // ---- x resident in registers: 4 rows x 4 chunks x (lo,hi) ull -------
    ull xlo[4][4], xhi[4][4];
    #pragma unroll
    for (int r = 0; r < 4; ++r) {
        const float* xr = x + (size_t)(rowBase + warp * 4 + r) * N_IN;
        #pragma unroll
        for (int c = 0; c < 4; ++c) {
            const ulonglong2 v = *(const ulonglong2*)(xr + c * 128 + lane * 4);
            xlo[r][c] = v.x;
            xhi[r][c] = v.y;
        }
    }

    // ---- zero evaluated-act store ---------------------------------------
    {
        float4* p = (float4*)sEval;
        const float4 z4 = make_float4(0.f, 0.f, 0.f, 0.f);
        for (int e = tid; e < TB * EVS / 4; e += THREADS) p[e] = z4;
    }
    // stage in-group W block for group 0
    if (tid < G * G) {
        int r = tid / G, c = tid % G;
        sWblk[0][r][c] = W[(size_t)r * N_NODES + (N_IN + c)];
    }
    // prefetch group 0 chunk 0 of W (8 rows x 4 lines = 32 lines, 1/lane)
    if (warp == 0)
        l1_prefetch(W + (size_t)(lane >> 2) * N_NODES + (lane & 3) * 32);
    __syncthreads();

    float* ev0 = sEval + (warp * 4 + 0) * EVS;
    float* ev1 = sEval + (warp * 4 + 1) * EVS;
    float* ev2 = sEval + (warp * 4 + 2) * EVS;
    float* ev3 = sEval + (warp * 4 + 3) * EVS;

    // ---- sequential scan over node groups -------------------------------
    for (int grp = 0; grp < NGROUPS; ++grp) {
        const int ib = grp * G;
        const float* Wg = W + (size_t)ib * N_NODES;
        const int nB  = (ib + 127) & ~127;       // part-B cols (rounded; over-
        const int nLW = N_IN + nB;               // read hits zeroed acts)

        ull acc[4][G];
        #pragma unroll
        for (int r = 0; r < 4; ++r)
            #pragma unroll
            for (int g = 0; g < G; ++g) acc[r][g] = 0ull;

        // --- part A: input cols, acts from registers --------------------
        #pragma unroll
        for (int c = 0; c < 4; ++c) {
            const int colW = c * 128 + lane * 4;
            if (warp == 0) {                     // prefetch next chunk's W
                const int nc = (c + 1) * 128;
                if (nc < nLW)
                    l1_prefetch(Wg + (size_t)(lane >> 2) * N_NODES + nc + (lane & 3) * 32);
            }
            #pragma unroll
            for (int g = 0; g < G; ++g) {
                const ulonglong2 wv = *(const ulonglong2*)(Wg + (size_t)g * N_NODES + colW);
                acc[0][g] = ffma2(wv.x, xlo[0][c], acc[0][g]);
                acc[0][g] = ffma2(wv.y, xhi[0][c], acc[0][g]);
                acc[1][g] = ffma2(wv.x, xlo[1][c], acc[1][g]);
                acc[1][g] = ffma2(wv.y, xhi[1][c], acc[1][g]);
                acc[2][g] = ffma2(wv.x, xlo[2][c], acc[2][g]);
                acc[2][g] = ffma2(wv.y, xhi[2][c], acc[2][g]);
                acc[3][g] = ffma2(wv.x, xlo[3][c], acc[3][g]);
                acc[3][g] = ffma2(wv.y, xhi[3][c], acc[3][g]);
            }
        }

        // --- part B: evaluated cols, acts from smem ----------------------
        #pragma unroll 1
        for (int base = 0; base < nB; base += 128) {
            const int j = base + lane * 4;
            const ulonglong2 a0 = *(const ulonglong2*)(ev0 + j);
            const ulonglong2 a1 = *(const ulonglong2*)(ev1 + j);
            const ulonglong2 a2 = *(const ulonglong2*)(ev2 + j);
            const ulonglong2 a3 = *(const ulonglong2*)(ev3 + j);
            if (warp == 0) {
                const int nc = N_IN + base + 128;
                if (nc < nLW)
                    l1_prefetch(Wg + (size_t)(lane >> 2) * N_NODES + nc + (lane & 3) * 32);
            }
            const int colW = N_IN + j;
            #pragma unroll
            for (int g = 0; g < G; ++g) {
                const ulonglong2 wv = *(const ulonglong2*)(Wg + (size_t)g * N_NODES + colW);
                acc[0][g] = ffma2(wv.x, a0.x, acc[0][g]);
                acc[0][g] = ffma2(wv.y, a0.y, acc[0][g]);
                acc[1][g] = ffma2(wv.x, a1.x, acc[1][g]);
                acc[1][g] = ffma2(wv.y, a1.y, acc[1][g]);
                acc[2][g] = ffma2(wv.x, a2.x, acc[2][g]);
                acc[2][g] = ffma2(wv.y, a2.y, acc[2][g]);
                acc[3][g] = ffma2(wv.x, a3.x, acc[3][g]);
                acc[3][g] = ffma2(wv.y, a3.y, acc[3][g]);
            }
        }

        // --- fold packed halves, butterfly reduce, add bias --------------
        float s[4][G];
        #pragma unroll
        for (int g = 0; g < G; ++g) {
            const float bg = b[ib + g];
            #pragma unroll
            for (int r = 0; r < 4; ++r) {
                float v = lo32(acc[r][g]) + hi32(acc[r][g]);
                #pragma unroll
                for (int sh = 16; sh > 0; sh >>= 1)
                    v += __shfl_xor_sync(0xffffffffu, v, sh);
                s[r][g] = v + bg;
            }
        }

        // --- serial in-group triangular tail (redundant on all lanes) ----
        const float (*blk)[G + 1] = sWblk[grp & 1];
        #pragma unroll
        for (int g = 0; g < G; ++g) {
            float o[4];
            #pragma unroll
            for (int r = 0; r < 4; ++r) o[r] = sigmoid5(s[r][g]);
            #pragma unroll
            for (int g2 = g + 1; g2 < G; ++g2) {
                const float wt = blk[g2][g];
                #pragma unroll
                for (int r = 0; r < 4; ++r) s[r][g2] = fmaf(wt, o[r], s[r][g2]);
            }
            if (lane == 0) {
                ev0[ib + g] = o[0];
                ev1[ib + g] = o[1];
                ev2[ib + g] = o[2];
                ev3[ib + g] = o[3];
            }
        }

        // --- prep next group: stage W block + prefetch its chunk 0 -------
        const int ibn = ib + G;
        if (ibn < N_EVAL) {
            if (tid < G * G) {
                int r = tid / G, c = tid % G;
                sWblk[(grp + 1) & 1][r][c] =
                    W[(size_t)(ibn + r) * N_NODES + (N_IN + ibn + c)];
            }
            if (warp == 0)
                l1_prefetch(W + (size_t)(ibn + (lane >> 2)) * N_NODES + (lane & 3) * 32);
        }
        __syncthreads();   // publish sWblk (dbl-buffered); keep W lockstep
    }

    // ---- write output: last N_OUT evaluated cols ------------------------
    const int OUT_BASE = EVS - N_OUT;   // 1280
    for (int e = tid; e < TB * N_OUT; e += THREADS) {
        int r = e / N_OUT, c = e % N_OUT;
        out[(size_t)(rowBase + r) * N_OUT + c] = sEval[r * EVS + OUT_BASE + c];
    }
}

extern "C" void kernel_launch(void* const* d_in, const int* in_sizes, int n_in,
                              void* d_out, int out_size)
{
    const float* x = (const float*)d_in[0];   // [4096, 512]
    const float* W = (const float*)d_in[1];   // [1536, 2048]
    const float* b = (const float*)d_in[2];   // [1536]
    float* out = (float*)d_out;               // [4096, 256]

    const size_t smem = (size_t)TB * EVS * sizeof(float);   // 192 KB
    cudaFuncSetAttribute(neat_scan_kernel,
                         cudaFuncAttributeMaxDynamicSharedMemorySize, (int)smem);
    neat_scan_kernel<<<4096 / TB, THREADS, smem>>>(x, W, b, out);
}